// round 9
// baseline (speedup 1.0000x reference)
#include <cuda_runtime.h>
#include <cuda_bf16.h>
#include <math.h>
#include <stdint.h>

#define BB 2
#define TT 2048
#define DD 1024
#define HH 16
#define HD 64
#define MM (BB*TT)

// ---------------- scratch ----------------
__device__ __nv_bfloat16 g_xhi[(size_t)MM*DD];
__device__ __nv_bfloat16 g_xlo[(size_t)MM*DD];
__device__ __nv_bfloat16 g_qhi[(size_t)MM*DD];
__device__ __nv_bfloat16 g_qlo[(size_t)MM*DD];
__device__ __nv_bfloat16 g_khi[(size_t)MM*DD];
__device__ __nv_bfloat16 g_klo[(size_t)MM*DD];
__device__ __nv_bfloat16 g_vhi[(size_t)MM*DD];
__device__ __nv_bfloat16 g_vlo[(size_t)MM*DD];
__device__ __nv_bfloat16 g_ahi[(size_t)MM*DD];
__device__ __nv_bfloat16 g_alo[(size_t)MM*DD];
__device__ __nv_bfloat16 g_whi[4*(size_t)DD*DD];
__device__ __nv_bfloat16 g_wlo[4*(size_t)DD*DD];

// ---------------- helpers ----------------
__device__ __forceinline__ uint32_t smem_u32(const void* p) {
    uint32_t a;
    asm("{ .reg .u64 t; cvta.to.shared.u64 t, %1; cvt.u32.u64 %0, t; }" : "=r"(a) : "l"(p));
    return a;
}
__device__ __forceinline__ float fast_exp2(float x) {
    float y; asm("ex2.approx.ftz.f32 %0, %1;" : "=f"(y) : "f"(x)); return y;
}
__device__ __forceinline__ void bsplit(float v, __nv_bfloat16& h, __nv_bfloat16& l) {
    h = __float2bfloat16(v);
    l = __float2bfloat16(v - __bfloat162float(h));
}
__device__ __forceinline__ void mma_bf16(float* c, const uint32_t* a, uint32_t b0, uint32_t b1) {
    asm("mma.sync.aligned.m16n8k16.row.col.f32.bf16.bf16.f32 "
        "{%0,%1,%2,%3}, {%4,%5,%6,%7}, {%8,%9}, {%0,%1,%2,%3};"
        : "+f"(c[0]), "+f"(c[1]), "+f"(c[2]), "+f"(c[3])
        : "r"(a[0]), "r"(a[1]), "r"(a[2]), "r"(a[3]), "r"(b0), "r"(b1));
}
__device__ __forceinline__ void ldsm4(uint32_t addr, uint32_t* r) {
    asm volatile("ldmatrix.sync.aligned.m8n8.x4.shared.b16 {%0,%1,%2,%3}, [%4];"
        : "=r"(r[0]), "=r"(r[1]), "=r"(r[2]), "=r"(r[3]) : "r"(addr));
}
__device__ __forceinline__ void ldsm4t(uint32_t addr, uint32_t* r) {
    asm volatile("ldmatrix.sync.aligned.m8n8.x4.trans.shared.b16 {%0,%1,%2,%3}, [%4];"
        : "=r"(r[0]), "=r"(r[1]), "=r"(r[2]), "=r"(r[3]) : "r"(addr));
}
__device__ __forceinline__ void cpa(uint32_t dst, const void* src) {
    asm volatile("cp.async.ca.shared.global [%0], [%1], 16;" :: "r"(dst), "l"(src));
}
__device__ __forceinline__ void commitg() {
    asm volatile("cp.async.commit_group;" ::: "memory");
}
template<int N> __device__ __forceinline__ void waitg() {
    asm volatile("cp.async.wait_group %0;" :: "n"(N) : "memory");
}
__device__ __forceinline__ void packsplit(float x, float y, uint32_t& hi, uint32_t& lo) {
    asm("cvt.rn.bf16x2.f32 %0, %1, %2;" : "=r"(hi) : "f"(y), "f"(x));
    __nv_bfloat162 t = *(__nv_bfloat162*)&hi;
    float rx = x - __bfloat162float(t.x);
    float ry = y - __bfloat162float(t.y);
    asm("cvt.rn.bf16x2.f32 %0, %1, %2;" : "=r"(lo) : "f"(ry), "f"(rx));
}

// ---------------------------------------------------------------------------
__global__ void splitf(const float* __restrict__ in,
                       __nv_bfloat16* __restrict__ hi, __nv_bfloat16* __restrict__ lo)
{
    const int i = blockIdx.x * blockDim.x + threadIdx.x;
    float4 v = ((const float4*)in)[i];
    __nv_bfloat16 h0,h1,h2,h3,l0,l1,l2,l3;
    bsplit(v.x,h0,l0); bsplit(v.y,h1,l1); bsplit(v.z,h2,l2); bsplit(v.w,h3,l3);
    __nv_bfloat162* ph = (__nv_bfloat162*)hi;
    __nv_bfloat162* pl = (__nv_bfloat162*)lo;
    __nv_bfloat162 a; a.x=h0; a.y=h1; ph[2*i] = a;
    a.x=h2; a.y=h3; ph[2*i+1] = a;
    a.x=l0; a.y=l1; pl[2*i] = a;
    a.x=l2; a.y=l3; pl[2*i+1] = a;
}

__global__ void transp_split4(const float* __restrict__ W0, const float* __restrict__ W1,
                              const float* __restrict__ W2, const float* __restrict__ W3,
                              __nv_bfloat16* __restrict__ Bh, __nv_bfloat16* __restrict__ Bl)
{
    __shared__ float t[32][33];
    const int z = blockIdx.z;
    const float* A = (z == 0) ? W0 : (z == 1) ? W1 : (z == 2) ? W2 : W3;
    const size_t zo = (size_t)z * DD * DD;
    const int bx = blockIdx.x * 32, by = blockIdx.y * 32;
    const int x = threadIdx.x, y = threadIdx.y;
    #pragma unroll
    for (int i = 0; i < 32; i += 8)
        t[y + i][x] = A[(size_t)(by + y + i) * DD + bx + x];
    __syncthreads();
    #pragma unroll
    for (int i = 0; i < 32; i += 8) {
        float v = t[x][y + i];
        __nv_bfloat16 h, l; bsplit(v, h, l);
        const size_t o = zo + (size_t)(bx + y + i) * DD + by + x;
        Bh[o] = h; Bl[o] = l;
    }
}

// ---------------------------------------------------------------------------
// GEMM: split-bf16 mma.sync + ldmatrix + cp.async double buffer, 1 sync/iter.
// ---------------------------------------------------------------------------
#define G_AH 0
#define G_AL 8192
#define G_BH 16384
#define G_BL 24576
#define G_STG 32768
#define GEMM_SMEM 65536

#define GEMM_LOAD(IT, STG) { \
    const int k0_ = (IT) * 32; \
    _Pragma("unroll") \
    for (int q_ = 0; q_ < 8; q_++) { \
        int idx_ = q_ * 256 + tid; \
        int buf_ = idx_ >> 9, wi_ = idx_ & 511; \
        int row_ = wi_ >> 2, kc_ = wi_ & 3; \
        uint32_t dst_ = sb + (STG)*G_STG + buf_*8192 + row_*64 + ((kc_ ^ ((row_>>1)&3)) << 4); \
        const __nv_bfloat16* src_; \
        if      (buf_ == 0) src_ = Ahi + (size_t)(m0 + row_)*DD + k0_ + kc_*8; \
        else if (buf_ == 1) src_ = Alo + (size_t)(m0 + row_)*DD + k0_ + kc_*8; \
        else if (buf_ == 2) src_ = Bhi + (size_t)(n0 + row_)*DD + k0_ + kc_*8; \
        else                src_ = Blo + (size_t)(n0 + row_)*DD + k0_ + kc_*8; \
        cpa(dst_, src_); \
    } }

template<int MODE>
__global__ __launch_bounds__(256, 2)
void mma_gemm(const __nv_bfloat16* __restrict__ Ahi, const __nv_bfloat16* __restrict__ Alo,
              const __nv_bfloat16* __restrict__ Whi, const __nv_bfloat16* __restrict__ Wlo,
              const float* __restrict__ b0, const float* __restrict__ b1,
              const float* __restrict__ b2,
              float* __restrict__ outf,
              __nv_bfloat16* __restrict__ oh0, __nv_bfloat16* __restrict__ ol0,
              __nv_bfloat16* __restrict__ oh1, __nv_bfloat16* __restrict__ ol1,
              __nv_bfloat16* __restrict__ oh2, __nv_bfloat16* __restrict__ ol2)
{
    extern __shared__ __align__(1024) char smem[];
    const uint32_t sb = smem_u32(smem);
    const int tid  = threadIdx.x;
    const int wid  = tid >> 5, lane = tid & 31;
    const int g    = lane >> 2, t4 = lane & 3;
    const int grp  = lane >> 3, wi = lane & 7;
    const int wm   = wid & 3,  wn = wid >> 2;
    const int m0   = blockIdx.y * 128, n0 = blockIdx.x * 128;
    const int z    = blockIdx.z;

    const size_t WSZ = (size_t)DD * DD;
    const __nv_bfloat16* Bhi = Whi + (size_t)z * WSZ;
    const __nv_bfloat16* Blo = Wlo + (size_t)z * WSZ;
    const float* bias = (z == 0) ? b0 : (z == 1) ? b1 : b2;
    __nv_bfloat16* outh = (z == 0) ? oh0 : (z == 1) ? oh1 : oh2;
    __nv_bfloat16* outl = (z == 0) ? ol0 : (z == 1) ? ol1 : ol2;

    float c[2][8][4];
    #pragma unroll
    for (int mb = 0; mb < 2; mb++)
        #pragma unroll
        for (int nb = 0; nb < 8; nb++)
            #pragma unroll
            for (int j = 0; j < 4; j++) c[mb][nb][j] = 0.f;

    GEMM_LOAD(0, 0); commitg();

    for (int it = 0; it < DD/32; it++) {
        waitg<0>();
        __syncthreads();
        if (it + 1 < DD/32) { GEMM_LOAD(it+1, (it+1)&1); commitg(); }
        const uint32_t base = sb + (it & 1) * G_STG;

        #pragma unroll
        for (int ks = 0; ks < 2; ks++) {
            uint32_t ah[2][4], al[2][4];
            #pragma unroll
            for (int mb = 0; mb < 2; mb++) {
                const int row = wm*32 + mb*16 + (grp & 1)*8 + wi;
                const int kb  = ks*32 + (grp >> 1)*16;
                const uint32_t off = row*64 + ((((kb >> 4) ^ ((row >> 1) & 3))) << 4);
                ldsm4(base + G_AH + off, ah[mb]);
                ldsm4(base + G_AL + off, al[mb]);
            }
            #pragma unroll
            for (int nbp = 0; nbp < 4; nbp++) {
                const int rowb = wn*64 + nbp*16 + (grp >> 1)*8 + wi;
                const int kb2  = ks*32 + (grp & 1)*16;
                const uint32_t offb = rowb*64 + ((((kb2 >> 4) ^ ((rowb >> 1) & 3))) << 4);
                uint32_t bh[4], bl[4];
                ldsm4(base + G_BH + offb, bh);
                ldsm4(base + G_BL + offb, bl);
                #pragma unroll
                for (int mb = 0; mb < 2; mb++) {
                    mma_bf16(c[mb][2*nbp],   ah[mb], bh[0], bh[1]);
                    mma_bf16(c[mb][2*nbp],   al[mb], bh[0], bh[1]);
                    mma_bf16(c[mb][2*nbp],   ah[mb], bl[0], bl[1]);
                    mma_bf16(c[mb][2*nbp+1], ah[mb], bh[2], bh[3]);
                    mma_bf16(c[mb][2*nbp+1], al[mb], bh[2], bh[3]);
                    mma_bf16(c[mb][2*nbp+1], ah[mb], bl[2], bl[3]);
                }
            }
        }
    }

    #pragma unroll
    for (int mb = 0; mb < 2; mb++) {
        const int row = m0 + wm*32 + mb*16 + g;
        #pragma unroll
        for (int nb = 0; nb < 8; nb++) {
            const int col = n0 + wn*64 + nb*8 + t4*2;
            const float bx = bias[col], by = bias[col+1];
            const float v0x = c[mb][nb][0] + bx, v0y = c[mb][nb][1] + by;
            const float v1x = c[mb][nb][2] + bx, v1y = c[mb][nb][3] + by;
            if (MODE == 0) {
                *(float2*)(outf + (size_t)row * DD + col)       = make_float2(v0x, v0y);
                *(float2*)(outf + (size_t)(row + 8) * DD + col) = make_float2(v1x, v1y);
            } else {
                const int h = col >> 6, d = col & 63;
                const int b0r = row >> 11, t0 = row & (TT-1);
                const int b1r = (row+8) >> 11, t1 = (row+8) & (TT-1);
                const size_t o0 = (((size_t)(b0r*HH + h) * TT + t0) * HD) + d;
                const size_t o1 = (((size_t)(b1r*HH + h) * TT + t1) * HD) + d;
                __nv_bfloat16 hx,hy,lx,ly;
                bsplit(v0x,hx,lx); bsplit(v0y,hy,ly);
                { __nv_bfloat162 p; p.x=hx; p.y=hy; *(__nv_bfloat162*)(outh+o0)=p;
                  p.x=lx; p.y=ly; *(__nv_bfloat162*)(outl+o0)=p; }
                bsplit(v1x,hx,lx); bsplit(v1y,hy,ly);
                { __nv_bfloat162 p; p.x=hx; p.y=hy; *(__nv_bfloat162*)(outh+o1)=p;
                  p.x=lx; p.y=ly; *(__nv_bfloat162*)(outl+o1)=p; }
            }
        }
    }
}

// ---------------------------------------------------------------------------
// Flash attention v4: 128-query CTA, 4 warps x 32 q-rows (2 m-blocks each),
// 128 threads, 2 CTAs/SM (reg budget 256). K/V b-frags reused across the two
// m-blocks -> MMA:LDSM ratio 2.4 (was 0.67). K and V double-buffered.
// SMEM 96KB: Q hi/lo 32K + K stages 2x16K + V stages 2x16K.
// ---------------------------------------------------------------------------
#define A_QH 0
#define A_QL 16384
#define A_KST(s) (32768 + (s)*16384)
#define A_VST(s) (65536 + (s)*16384)
#define ATT_SMEM 98304

#define KV_PREFETCH(KT, STG) { \
    _Pragma("unroll") \
    for (int q_ = 0; q_ < 16; q_++) { \
        int idx_ = q_ * 128 + tid; \
        int arr_ = idx_ >> 9, wi2_ = idx_ & 511; \
        int row_ = wi2_ >> 3, ch_ = wi2_ & 7; \
        uint32_t base_ = (arr_ < 2) ? A_KST(STG) : A_VST(STG); \
        uint32_t dst_ = sb + base_ + (arr_ & 1)*8192 + row_*128 + ((ch_ ^ (row_ & 7)) << 4); \
        const __nv_bfloat16* p_ = (arr_ == 0) ? Kh : (arr_ == 1) ? Kl : (arr_ == 2) ? Vh : Vl; \
        cpa(dst_, p_ + bo + (size_t)((KT)*64 + row_)*HD + ch_*8); \
    } }

__global__ __launch_bounds__(128, 2)
void attn_mma(const __nv_bfloat16* __restrict__ Qh, const __nv_bfloat16* __restrict__ Ql,
              const __nv_bfloat16* __restrict__ Kh, const __nv_bfloat16* __restrict__ Kl,
              const __nv_bfloat16* __restrict__ Vh, const __nv_bfloat16* __restrict__ Vl,
              __nv_bfloat16* __restrict__ Oh, __nv_bfloat16* __restrict__ Ol)
{
    extern __shared__ __align__(1024) char smem[];
    const uint32_t sb = smem_u32(smem);
    const int tid  = threadIdx.x, lane = tid & 31, warp = tid >> 5;
    const int g    = lane >> 2, t4 = lane & 3;
    const int grp  = lane >> 3, wi = lane & 7;
    const int qt   = (int)gridDim.x - 1 - (int)blockIdx.x;
    const int bh   = blockIdx.y, b = bh >> 4, h = bh & 15;
    const size_t bo = (size_t)bh * TT * HD;

    // group 0: Q tile (128 rows, hi+lo) + KV stage 0
    #pragma unroll
    for (int q = 0; q < 16; q++) {
        int idx = q * 128 + tid;
        int arr = idx >> 10, w2 = idx & 1023;
        int row = w2 >> 3, ch = w2 & 7;
        uint32_t dst = sb + arr*16384 + row*128 + ((ch ^ (row & 7)) << 4);
        const __nv_bfloat16* src = (arr ? Ql : Qh) + bo + (size_t)(qt*128 + row)*HD + ch*8;
        cpa(dst, src);
    }
    KV_PREFETCH(0, 0); commitg();

    const float LOG2E  = 1.4426950408889634f;
    const float scale2 = 0.125f * LOG2E;
    const float slope2 = exp2f(-0.5f * (float)(h + 1)) * LOG2E;

    float cO[2][8][4];
    #pragma unroll
    for (int mb = 0; mb < 2; mb++)
        #pragma unroll
        for (int nb = 0; nb < 8; nb++)
            #pragma unroll
            for (int j = 0; j < 4; j++) cO[mb][nb][j] = 0.f;
    float mra[2][2], lra[2][2];
    #pragma unroll
    for (int mb = 0; mb < 2; mb++) { mra[mb][0] = mra[mb][1] = -1e30f; lra[mb][0] = lra[mb][1] = 0.f; }

    const int NT = 2*qt + 2;              // 64-wide key tiles
    const int wrow0 = qt*128 + warp*32;   // warp's first q row

    for (int kt = 0; kt < NT; kt++) {
        waitg<0>();
        __syncthreads();
        if (kt + 1 < NT) { KV_PREFETCH(kt+1, (kt+1)&1); commitg(); }
        const uint32_t stbK = sb + A_KST(kt & 1);
        const uint32_t stbV = sb + A_VST(kt & 1);

        if (kt*64 > wrow0 + 31) continue;   // fully masked for this warp

        // ---- S = Q K^T (3-term split, 2 m-blocks share K frags) ----
        float cS[2][8][4];
        #pragma unroll
        for (int mb = 0; mb < 2; mb++)
            #pragma unroll
            for (int nb = 0; nb < 8; nb++)
                #pragma unroll
                for (int j = 0; j < 4; j++) cS[mb][nb][j] = 0.f;

        #pragma unroll
        for (int s = 0; s < 4; s++) {
            uint32_t qfh[2][4], qfl[2][4];
            #pragma unroll
            for (int mb = 0; mb < 2; mb++) {
                const int row = warp*32 + mb*16 + (grp & 1)*8 + wi;
                const int cb  = s*32 + (grp >> 1)*16;
                const uint32_t off = row*128 + ((uint32_t)cb ^ (uint32_t)((row & 7) << 4));
                ldsm4(sb + A_QH + off, qfh[mb]);
                ldsm4(sb + A_QL + off, qfl[mb]);
            }
            #pragma unroll
            for (int nbp = 0; nbp < 4; nbp++) {
                const int rowk = nbp*16 + (grp >> 1)*8 + wi;
                const int cbk  = s*32 + (grp & 1)*16;
                const uint32_t off = rowk*128 + ((uint32_t)cbk ^ (uint32_t)((rowk & 7) << 4));
                uint32_t kh4[4], kl4[4];
                ldsm4(stbK + off, kh4);
                ldsm4(stbK + 8192 + off, kl4);
                #pragma unroll
                for (int mb = 0; mb < 2; mb++) {
                    mma_bf16(cS[mb][2*nbp],   qfh[mb], kh4[0], kh4[1]);
                    mma_bf16(cS[mb][2*nbp],   qfl[mb], kh4[0], kh4[1]);
                    mma_bf16(cS[mb][2*nbp],   qfh[mb], kl4[0], kl4[1]);
                    mma_bf16(cS[mb][2*nbp+1], qfh[mb], kh4[2], kh4[3]);
                    mma_bf16(cS[mb][2*nbp+1], qfl[mb], kh4[2], kh4[3]);
                    mma_bf16(cS[mb][2*nbp+1], qfh[mb], kl4[2], kl4[3]);
                }
            }
        }

        // ---- scale + ALiBi + causal + online softmax (per m-block) ----
        const bool diag = (kt*64 + 63 > wrow0);
        #pragma unroll
        for (int mb = 0; mb < 2; mb++) {
            const int r0 = wrow0 + mb*16 + g, r1 = r0 + 8;
            float mx0 = -1e30f, mx1 = -1e30f;
            #pragma unroll
            for (int nb = 0; nb < 8; nb++) {
                const int k0i = kt*64 + nb*8 + t4*2;
                const float b0f = -slope2 * (float)(TT - 1 - k0i);
                const float b1f = -slope2 * (float)(TT - 2 - k0i);
                float v0 = fmaf(cS[mb][nb][0], scale2, b0f);
                float v1 = fmaf(cS[mb][nb][1], scale2, b1f);
                float v2 = fmaf(cS[mb][nb][2], scale2, b0f);
                float v3 = fmaf(cS[mb][nb][3], scale2, b1f);
                if (diag) {
                    if (k0i     > r0) v0 = -1e30f;
                    if (k0i + 1 > r0) v1 = -1e30f;
                    if (k0i     > r1) v2 = -1e30f;
                    if (k0i + 1 > r1) v3 = -1e30f;
                }
                cS[mb][nb][0] = v0; cS[mb][nb][1] = v1;
                cS[mb][nb][2] = v2; cS[mb][nb][3] = v3;
                mx0 = fmaxf(mx0, fmaxf(v0, v1));
                mx1 = fmaxf(mx1, fmaxf(v2, v3));
            }
            mx0 = fmaxf(mx0, __shfl_xor_sync(0xffffffffu, mx0, 1));
            mx0 = fmaxf(mx0, __shfl_xor_sync(0xffffffffu, mx0, 2));
            mx1 = fmaxf(mx1, __shfl_xor_sync(0xffffffffu, mx1, 1));
            mx1 = fmaxf(mx1, __shfl_xor_sync(0xffffffffu, mx1, 2));
            const float mn0 = fmaxf(mra[mb][0], mx0), mn1 = fmaxf(mra[mb][1], mx1);
            const float co0 = fast_exp2(mra[mb][0] - mn0), co1 = fast_exp2(mra[mb][1] - mn1);
            mra[mb][0] = mn0; mra[mb][1] = mn1;
            float s0 = 0.f, s1 = 0.f;
            #pragma unroll
            for (int nb = 0; nb < 8; nb++) {
                cS[mb][nb][0] = fast_exp2(cS[mb][nb][0] - mn0);
                cS[mb][nb][1] = fast_exp2(cS[mb][nb][1] - mn0);
                cS[mb][nb][2] = fast_exp2(cS[mb][nb][2] - mn1);
                cS[mb][nb][3] = fast_exp2(cS[mb][nb][3] - mn1);
                s0 += cS[mb][nb][0] + cS[mb][nb][1];
                s1 += cS[mb][nb][2] + cS[mb][nb][3];
            }
            s0 += __shfl_xor_sync(0xffffffffu, s0, 1);
            s0 += __shfl_xor_sync(0xffffffffu, s0, 2);
            s1 += __shfl_xor_sync(0xffffffffu, s1, 1);
            s1 += __shfl_xor_sync(0xffffffffu, s1, 2);
            lra[mb][0] = lra[mb][0] * co0 + s0;
            lra[mb][1] = lra[mb][1] * co1 + s1;
            #pragma unroll
            for (int nb = 0; nb < 8; nb++) {
                cO[mb][nb][0] *= co0; cO[mb][nb][1] *= co0;
                cO[mb][nb][2] *= co1; cO[mb][nb][3] *= co1;
            }
        }

        // ---- O += P V (V frags shared across the 2 m-blocks) ----
        #pragma unroll
        for (int s = 0; s < 4; s++) {
            uint32_t aPh[2][4], aPl[2][4];
            #pragma unroll
            for (int mb = 0; mb < 2; mb++) {
                packsplit(cS[mb][2*s][0],   cS[mb][2*s][1],   aPh[mb][0], aPl[mb][0]);
                packsplit(cS[mb][2*s][2],   cS[mb][2*s][3],   aPh[mb][1], aPl[mb][1]);
                packsplit(cS[mb][2*s+1][0], cS[mb][2*s+1][1], aPh[mb][2], aPl[mb][2]);
                packsplit(cS[mb][2*s+1][2], cS[mb][2*s+1][3], aPh[mb][3], aPl[mb][3]);
            }
            #pragma unroll
            for (int nbp = 0; nbp < 4; nbp++) {
                const int rowv = s*16 + (grp & 1)*8 + wi;
                const int cbv  = nbp*32 + (grp >> 1)*16;
                const uint32_t off = rowv*128 + ((uint32_t)cbv ^ (uint32_t)((rowv & 7) << 4));
                uint32_t vh4[4], vl4[4];
                ldsm4t(stbV + off, vh4);
                ldsm4t(stbV + 8192 + off, vl4);
                #pragma unroll
                for (int mb = 0; mb < 2; mb++) {
                    mma_bf16(cO[mb][2*nbp],   aPh[mb], vh4[0], vh4[1]);
                    mma_bf16(cO[mb][2*nbp],   aPl[mb], vh4[0], vh4[1]);
                    mma_bf16(cO[mb][2*nbp],   aPh[mb], vl4[0], vl4[1]);
                    mma_bf16(cO[mb][2*nbp+1], aPh[mb], vh4[2], vh4[3]);
                    mma_bf16(cO[mb][2*nbp+1], aPl[mb], vh4[2], vh4[3]);
                    mma_bf16(cO[mb][2*nbp+1], aPh[mb], vl4[2], vl4[3]);
                }
            }
        }
    }

    // ---- normalize + write split bf16 ----
    #pragma unroll
    for (int mb = 0; mb < 2; mb++) {
        const float i0 = 1.f / lra[mb][0], i1 = 1.f / lra[mb][1];
        const int t0 = wrow0 + mb*16 + g;
        #pragma unroll
        for (int nb = 0; nb < 8; nb++) {
            const int d = h*HD + nb*8 + t4*2;
            const size_t o0 = (size_t)(b*TT + t0) * DD + d;
            const size_t o1 = o0 + (size_t)8 * DD;
            __nv_bfloat16 hx,hy,lx,ly;
            bsplit(cO[mb][nb][0]*i0, hx, lx); bsplit(cO[mb][nb][1]*i0, hy, ly);
            { __nv_bfloat162 p; p.x=hx; p.y=hy; *(__nv_bfloat162*)(Oh+o0)=p;
              p.x=lx; p.y=ly; *(__nv_bfloat162*)(Ol+o0)=p; }
            bsplit(cO[mb][nb][2]*i1, hx, lx); bsplit(cO[mb][nb][3]*i1, hy, ly);
            { __nv_bfloat162 p; p.x=hx; p.y=hy; *(__nv_bfloat162*)(Oh+o1)=p;
              p.x=lx; p.y=ly; *(__nv_bfloat162*)(Ol+o1)=p; }
        }
    }
}

// ---------------------------------------------------------------------------
extern "C" void kernel_launch(void* const* d_in, const int* in_sizes, int n_in,
                              void* d_out, int out_size)
{
    const float* x  = (const float*)d_in[0];
    const float* Wq = (const float*)d_in[1];
    const float* bq = (const float*)d_in[2];
    const float* Wk = (const float*)d_in[3];
    const float* bk = (const float*)d_in[4];
    const float* Wv = (const float*)d_in[5];
    const float* bv = (const float*)d_in[6];
    const float* Wo = (const float*)d_in[7];
    const float* bo = (const float*)d_in[8];
    float* out = (float*)d_out;

    __nv_bfloat16 *xhi,*xlo,*qhi,*qlo,*khi,*klo,*vhi,*vlo,*ahi,*alo,*whi,*wlo;
    cudaGetSymbolAddress((void**)&xhi, g_xhi);
    cudaGetSymbolAddress((void**)&xlo, g_xlo);
    cudaGetSymbolAddress((void**)&qhi, g_qhi);
    cudaGetSymbolAddress((void**)&qlo, g_qlo);
    cudaGetSymbolAddress((void**)&khi, g_khi);
    cudaGetSymbolAddress((void**)&klo, g_klo);
    cudaGetSymbolAddress((void**)&vhi, g_vhi);
    cudaGetSymbolAddress((void**)&vlo, g_vlo);
    cudaGetSymbolAddress((void**)&ahi, g_ahi);
    cudaGetSymbolAddress((void**)&alo, g_alo);
    cudaGetSymbolAddress((void**)&whi, g_whi);
    cudaGetSymbolAddress((void**)&wlo, g_wlo);

    cudaFuncSetAttribute(mma_gemm<0>, cudaFuncAttributeMaxDynamicSharedMemorySize, GEMM_SMEM);
    cudaFuncSetAttribute(mma_gemm<1>, cudaFuncAttributeMaxDynamicSharedMemorySize, GEMM_SMEM);
    cudaFuncSetAttribute(attn_mma,   cudaFuncAttributeMaxDynamicSharedMemorySize, ATT_SMEM);

    const size_t WSZ = (size_t)DD * DD;

    splitf<<<(MM*DD/4)/256, 256>>>(x, xhi, xlo);
    transp_split4<<<dim3(32, 32, 4), dim3(32, 8)>>>(Wq, Wk, Wv, Wo, whi, wlo);

    mma_gemm<1><<<dim3(DD/128, MM/128, 3), 256, GEMM_SMEM>>>(
        xhi, xlo, whi, wlo, bq, bk, bv, nullptr,
        qhi, qlo, khi, klo, vhi, vlo);

    attn_mma<<<dim3(TT/128, BB*HH), 128, ATT_SMEM>>>(qhi, qlo, khi, klo, vhi, vlo, ahi, alo);

    mma_gemm<0><<<dim3(DD/128, MM/128, 1), 256, GEMM_SMEM>>>(
        ahi, alo, whi + 3*WSZ, wlo + 3*WSZ, bo, bo, bo, out,
        nullptr, nullptr, nullptr, nullptr, nullptr, nullptr);
}

// round 10
// speedup vs baseline: 1.3535x; 1.3535x over previous
#include <cuda_runtime.h>
#include <cuda_fp16.h>
#include <math.h>
#include <stdint.h>

#define BB 2
#define TT 2048
#define DD 1024
#define HH 16
#define HD 64
#define MM (BB*TT)

// ---------------- scratch (all fp16 now) ----------------
__device__ __half g_xh[(size_t)MM*DD];
__device__ __half g_qh[(size_t)MM*DD];
__device__ __half g_ql[(size_t)MM*DD];
__device__ __half g_kh[(size_t)MM*DD];
__device__ __half g_kl[(size_t)MM*DD];
__device__ __half g_vh[(size_t)MM*DD];
__device__ __half g_vl[(size_t)MM*DD];
__device__ __half g_ah[(size_t)MM*DD];
__device__ __half g_wh[4*(size_t)DD*DD];
__device__ __half g_wl[4*(size_t)DD*DD];

// ---------------- helpers ----------------
__device__ __forceinline__ uint32_t smem_u32(const void* p) {
    uint32_t a;
    asm("{ .reg .u64 t; cvta.to.shared.u64 t, %1; cvt.u32.u64 %0, t; }" : "=r"(a) : "l"(p));
    return a;
}
__device__ __forceinline__ float fast_exp2(float x) {
    float y; asm("ex2.approx.ftz.f32 %0, %1;" : "=f"(y) : "f"(x)); return y;
}
__device__ __forceinline__ void hsplit(float v, __half& h, __half& l) {
    h = __float2half_rn(v);
    l = __float2half_rn(v - __half2float(h));
}
__device__ __forceinline__ void mma_f16(float* c, const uint32_t* a, uint32_t b0, uint32_t b1) {
    asm("mma.sync.aligned.m16n8k16.row.col.f32.f16.f16.f32 "
        "{%0,%1,%2,%3}, {%4,%5,%6,%7}, {%8,%9}, {%0,%1,%2,%3};"
        : "+f"(c[0]), "+f"(c[1]), "+f"(c[2]), "+f"(c[3])
        : "r"(a[0]), "r"(a[1]), "r"(a[2]), "r"(a[3]), "r"(b0), "r"(b1));
}
__device__ __forceinline__ void ldsm4(uint32_t addr, uint32_t* r) {
    asm volatile("ldmatrix.sync.aligned.m8n8.x4.shared.b16 {%0,%1,%2,%3}, [%4];"
        : "=r"(r[0]), "=r"(r[1]), "=r"(r[2]), "=r"(r[3]) : "r"(addr));
}
__device__ __forceinline__ void ldsm4t(uint32_t addr, uint32_t* r) {
    asm volatile("ldmatrix.sync.aligned.m8n8.x4.trans.shared.b16 {%0,%1,%2,%3}, [%4];"
        : "=r"(r[0]), "=r"(r[1]), "=r"(r[2]), "=r"(r[3]) : "r"(addr));
}
__device__ __forceinline__ void cpa(uint32_t dst, const void* src) {
    asm volatile("cp.async.ca.shared.global [%0], [%1], 16;" :: "r"(dst), "l"(src));
}
__device__ __forceinline__ void commitg() {
    asm volatile("cp.async.commit_group;" ::: "memory");
}
template<int N> __device__ __forceinline__ void waitg() {
    asm volatile("cp.async.wait_group %0;" :: "n"(N) : "memory");
}
__device__ __forceinline__ uint32_t pack2h(float x, float y) {
    uint32_t r; asm("cvt.rn.f16x2.f32 %0, %1, %2;" : "=r"(r) : "f"(y), "f"(x)); return r;
}

// ---------------------------------------------------------------------------
__global__ void tohalf(const float* __restrict__ in, __half* __restrict__ out)
{
    const int i = blockIdx.x * blockDim.x + threadIdx.x;
    float4 v = ((const float4*)in)[i];
    __half2* p = (__half2*)out;
    p[2*i]   = __floats2half2_rn(v.x, v.y);
    p[2*i+1] = __floats2half2_rn(v.z, v.w);
}

// W transposed, scaled by 512, split to fp16 hi/lo
__global__ void transp_split4(const float* __restrict__ W0, const float* __restrict__ W1,
                              const float* __restrict__ W2, const float* __restrict__ W3,
                              __half* __restrict__ Bh, __half* __restrict__ Bl)
{
    __shared__ float t[32][33];
    const int z = blockIdx.z;
    const float* A = (z == 0) ? W0 : (z == 1) ? W1 : (z == 2) ? W2 : W3;
    const size_t zo = (size_t)z * DD * DD;
    const int bx = blockIdx.x * 32, by = blockIdx.y * 32;
    const int x = threadIdx.x, y = threadIdx.y;
    #pragma unroll
    for (int i = 0; i < 32; i += 8)
        t[y + i][x] = A[(size_t)(by + y + i) * DD + bx + x];
    __syncthreads();
    #pragma unroll
    for (int i = 0; i < 32; i += 8) {
        float v = t[x][y + i] * 512.f;
        __half h, l; hsplit(v, h, l);
        const size_t o = zo + (size_t)(bx + y + i) * DD + by + x;
        Bh[o] = h; Bl[o] = l;
    }
}

// ---------------------------------------------------------------------------
// GEMM: fp16 2-term (A single fp16, W split hi/lo, W pre-scaled by 512).
// C = A·(Wh+Wl)/512 + bias. mma.sync f16 + ldmatrix + cp.async, 1 sync/iter.
// MODE 0: fp32 out. MODE 1: merged QKV, fp16 hi/lo scatter to (B,H,T,hd).
// ---------------------------------------------------------------------------
#define G_A  0
#define G_BH 8192
#define G_BL 16384
#define G_STG 24576
#define GEMM_SMEM 49152

#define GEMM_LOAD(IT, STG) { \
    const int k0_ = (IT) * 32; \
    _Pragma("unroll") \
    for (int q_ = 0; q_ < 6; q_++) { \
        int idx_ = q_ * 256 + tid; \
        int buf_ = idx_ >> 9, wi_ = idx_ & 511; \
        int row_ = wi_ >> 2, kc_ = wi_ & 3; \
        uint32_t dst_ = sb + (STG)*G_STG + buf_*8192 + row_*64 + ((kc_ ^ ((row_>>1)&3)) << 4); \
        const __half* src_; \
        if      (buf_ == 0) src_ = Ah  + (size_t)(m0 + row_)*DD + k0_ + kc_*8; \
        else if (buf_ == 1) src_ = Bhi + (size_t)(n0 + row_)*DD + k0_ + kc_*8; \
        else                src_ = Blo + (size_t)(n0 + row_)*DD + k0_ + kc_*8; \
        cpa(dst_, src_); \
    } }

template<int MODE>
__global__ __launch_bounds__(256, 2)
void mma_gemm(const __half* __restrict__ Ah,
              const __half* __restrict__ Whi, const __half* __restrict__ Wlo,
              const float* __restrict__ b0, const float* __restrict__ b1,
              const float* __restrict__ b2,
              float* __restrict__ outf,
              __half* __restrict__ oh0, __half* __restrict__ ol0,
              __half* __restrict__ oh1, __half* __restrict__ ol1,
              __half* __restrict__ oh2, __half* __restrict__ ol2)
{
    extern __shared__ __align__(1024) char smem[];
    const uint32_t sb = smem_u32(smem);
    const int tid  = threadIdx.x;
    const int wid  = tid >> 5, lane = tid & 31;
    const int g    = lane >> 2, t4 = lane & 3;
    const int grp  = lane >> 3, wi = lane & 7;
    const int wm   = wid & 3,  wn = wid >> 2;
    const int m0   = blockIdx.y * 128, n0 = blockIdx.x * 128;
    const int z    = blockIdx.z;

    const size_t WSZ = (size_t)DD * DD;
    const __half* Bhi = Whi + (size_t)z * WSZ;
    const __half* Blo = Wlo + (size_t)z * WSZ;
    const float* bias = (z == 0) ? b0 : (z == 1) ? b1 : b2;
    __half* outh = (z == 0) ? oh0 : (z == 1) ? oh1 : oh2;
    __half* outl = (z == 0) ? ol0 : (z == 1) ? ol1 : ol2;

    float c[2][8][4];
    #pragma unroll
    for (int mb = 0; mb < 2; mb++)
        #pragma unroll
        for (int nb = 0; nb < 8; nb++)
            #pragma unroll
            for (int j = 0; j < 4; j++) c[mb][nb][j] = 0.f;

    GEMM_LOAD(0, 0); commitg();

    for (int it = 0; it < DD/32; it++) {
        waitg<0>();
        __syncthreads();
        if (it + 1 < DD/32) { GEMM_LOAD(it+1, (it+1)&1); commitg(); }
        const uint32_t base = sb + (it & 1) * G_STG;

        #pragma unroll
        for (int ks = 0; ks < 2; ks++) {
            uint32_t ah[2][4];
            #pragma unroll
            for (int mb = 0; mb < 2; mb++) {
                const int row = wm*32 + mb*16 + (grp & 1)*8 + wi;
                const int kb  = ks*32 + (grp >> 1)*16;
                const uint32_t off = row*64 + ((((kb >> 4) ^ ((row >> 1) & 3))) << 4);
                ldsm4(base + G_A + off, ah[mb]);
            }
            #pragma unroll
            for (int nbp = 0; nbp < 4; nbp++) {
                const int rowb = wn*64 + nbp*16 + (grp >> 1)*8 + wi;
                const int kb2  = ks*32 + (grp & 1)*16;
                const uint32_t offb = rowb*64 + ((((kb2 >> 4) ^ ((rowb >> 1) & 3))) << 4);
                uint32_t bh[4], bl[4];
                ldsm4(base + G_BH + offb, bh);
                ldsm4(base + G_BL + offb, bl);
                #pragma unroll
                for (int mb = 0; mb < 2; mb++) {
                    mma_f16(c[mb][2*nbp],   ah[mb], bh[0], bh[1]);
                    mma_f16(c[mb][2*nbp],   ah[mb], bl[0], bl[1]);
                    mma_f16(c[mb][2*nbp+1], ah[mb], bh[2], bh[3]);
                    mma_f16(c[mb][2*nbp+1], ah[mb], bl[2], bl[3]);
                }
            }
        }
    }

    const float INV = 1.f / 512.f;
    #pragma unroll
    for (int mb = 0; mb < 2; mb++) {
        const int row = m0 + wm*32 + mb*16 + g;
        #pragma unroll
        for (int nb = 0; nb < 8; nb++) {
            const int col = n0 + wn*64 + nb*8 + t4*2;
            const float bx = bias[col], by = bias[col+1];
            const float v0x = c[mb][nb][0]*INV + bx, v0y = c[mb][nb][1]*INV + by;
            const float v1x = c[mb][nb][2]*INV + bx, v1y = c[mb][nb][3]*INV + by;
            if (MODE == 0) {
                *(float2*)(outf + (size_t)row * DD + col)       = make_float2(v0x, v0y);
                *(float2*)(outf + (size_t)(row + 8) * DD + col) = make_float2(v1x, v1y);
            } else {
                const int h = col >> 6, d = col & 63;
                const int b0r = row >> 11, t0 = row & (TT-1);
                const int b1r = (row+8) >> 11, t1 = (row+8) & (TT-1);
                const size_t o0 = (((size_t)(b0r*HH + h) * TT + t0) * HD) + d;
                const size_t o1 = (((size_t)(b1r*HH + h) * TT + t1) * HD) + d;
                __half hx,hy,lx,ly;
                hsplit(v0x,hx,lx); hsplit(v0y,hy,ly);
                { __half2 p; p.x=hx; p.y=hy; *(__half2*)(outh+o0)=p;
                  p.x=lx; p.y=ly; *(__half2*)(outl+o0)=p; }
                hsplit(v1x,hx,lx); hsplit(v1y,hy,ly);
                { __half2 p; p.x=hx; p.y=hy; *(__half2*)(outh+o1)=p;
                  p.x=lx; p.y=ly; *(__half2*)(outl+o1)=p; }
            }
        }
    }
}

// ---------------------------------------------------------------------------
// Flash attention (fp16 2-term): 64-query tiles, 128 threads, 2 CTAs/SM.
// S = Qh·(Kh+Kl); P packed single fp16; O += P·(Vh+Vl).
// SMEM 72KB: Q 8K + 2 stages x (Kh,Kl,Vh,Vl = 32K).
// ---------------------------------------------------------------------------
#define A_QH 0
#define A_ST(s) (8192 + (s)*32768)
#define ATT_SMEM 73728

#define KV_PREFETCH(KT, STG) { \
    _Pragma("unroll") \
    for (int q_ = 0; q_ < 16; q_++) { \
        int idx_ = q_ * 128 + tid; \
        int arr_ = idx_ >> 9, wi2_ = idx_ & 511; \
        int row_ = wi2_ >> 3, ch_ = wi2_ & 7; \
        uint32_t dst_ = sb + A_ST(STG) + arr_*8192 + row_*128 + ((ch_ ^ (row_ & 7)) << 4); \
        const __half* p_ = (arr_ == 0) ? Kh : (arr_ == 1) ? Kl : (arr_ == 2) ? Vh : Vl; \
        cpa(dst_, p_ + bo + (size_t)((KT)*64 + row_)*HD + ch_*8); \
    } }

__global__ __launch_bounds__(128, 2)
void attn_mma(const __half* __restrict__ Qh,
              const __half* __restrict__ Kh, const __half* __restrict__ Kl,
              const __half* __restrict__ Vh, const __half* __restrict__ Vl,
              __half* __restrict__ Oh)
{
    extern __shared__ __align__(1024) char smem[];
    const uint32_t sb = smem_u32(smem);
    const int tid  = threadIdx.x, lane = tid & 31, warp = tid >> 5;
    const int g    = lane >> 2, t4 = lane & 3;
    const int grp  = lane >> 3, wi = lane & 7;
    const int qt   = (int)gridDim.x - 1 - (int)blockIdx.x;
    const int bh   = blockIdx.y, b = bh >> 4, h = bh & 15;
    const size_t bo = (size_t)bh * TT * HD;

    // group 0: Q tile + KV stage 0
    #pragma unroll
    for (int q = 0; q < 4; q++) {
        int idx = q * 128 + tid;
        int row = idx >> 3, ch = idx & 7;
        uint32_t dst = sb + A_QH + row*128 + ((ch ^ (row & 7)) << 4);
        cpa(dst, Qh + bo + (size_t)(qt*64 + row)*HD + ch*8);
    }
    KV_PREFETCH(0, 0); commitg();

    const float LOG2E  = 1.4426950408889634f;
    const float scale2 = 0.125f * LOG2E;
    const float slope2 = exp2f(-0.5f * (float)(h + 1)) * LOG2E;

    float cO[8][4];
    #pragma unroll
    for (int nb = 0; nb < 8; nb++)
        #pragma unroll
        for (int j = 0; j < 4; j++) cO[nb][j] = 0.f;
    float mr0 = -1e30f, mr1 = -1e30f, lr0 = 0.f, lr1 = 0.f;
    uint32_t qfh[4][4];

    for (int kt = 0; kt <= qt; kt++) {
        waitg<0>();
        __syncthreads();
        if (kt < qt) { KV_PREFETCH(kt+1, (kt+1)&1); commitg(); }
        const uint32_t stb = sb + A_ST(kt & 1);

        if (kt == 0) {
            #pragma unroll
            for (int s = 0; s < 4; s++) {
                const int row = warp*16 + (grp & 1)*8 + wi;
                const int cb  = s*32 + (grp >> 1)*16;
                const uint32_t off = row*128 + ((uint32_t)cb ^ (uint32_t)((row & 7) << 4));
                ldsm4(sb + A_QH + off, qfh[s]);
            }
        }

        // ---- S = Q K^T (2-term) ----
        float cS[8][4];
        #pragma unroll
        for (int nb = 0; nb < 8; nb++)
            #pragma unroll
            for (int j = 0; j < 4; j++) cS[nb][j] = 0.f;

        #pragma unroll
        for (int s = 0; s < 4; s++) {
            #pragma unroll
            for (int nbp = 0; nbp < 4; nbp++) {
                const int row = nbp*16 + (grp >> 1)*8 + wi;
                const int cb  = s*32 + (grp & 1)*16;
                const uint32_t off = row*128 + ((uint32_t)cb ^ (uint32_t)((row & 7) << 4));
                uint32_t kh4[4], kl4[4];
                ldsm4(stb + off, kh4);
                ldsm4(stb + 8192 + off, kl4);
                mma_f16(cS[2*nbp],   qfh[s], kh4[0], kh4[1]);
                mma_f16(cS[2*nbp],   qfh[s], kl4[0], kl4[1]);
                mma_f16(cS[2*nbp+1], qfh[s], kh4[2], kh4[3]);
                mma_f16(cS[2*nbp+1], qfh[s], kl4[2], kl4[3]);
            }
        }

        // ---- scale + ALiBi + causal + online softmax ----
        const int r0 = qt*64 + warp*16 + g, r1 = r0 + 8;
        const bool diag = (kt == qt);
        float mx0 = -1e30f, mx1 = -1e30f;
        #pragma unroll
        for (int nb = 0; nb < 8; nb++) {
            const int k0i = kt*64 + nb*8 + t4*2;
            const float b0f = -slope2 * (float)(TT - 1 - k0i);
            const float b1f = -slope2 * (float)(TT - 2 - k0i);
            float v0 = fmaf(cS[nb][0], scale2, b0f);
            float v1 = fmaf(cS[nb][1], scale2, b1f);
            float v2 = fmaf(cS[nb][2], scale2, b0f);
            float v3 = fmaf(cS[nb][3], scale2, b1f);
            if (diag) {
                if (k0i     > r0) v0 = -1e30f;
                if (k0i + 1 > r0) v1 = -1e30f;
                if (k0i     > r1) v2 = -1e30f;
                if (k0i + 1 > r1) v3 = -1e30f;
            }
            cS[nb][0] = v0; cS[nb][1] = v1; cS[nb][2] = v2; cS[nb][3] = v3;
            mx0 = fmaxf(mx0, fmaxf(v0, v1));
            mx1 = fmaxf(mx1, fmaxf(v2, v3));
        }
        mx0 = fmaxf(mx0, __shfl_xor_sync(0xffffffffu, mx0, 1));
        mx0 = fmaxf(mx0, __shfl_xor_sync(0xffffffffu, mx0, 2));
        mx1 = fmaxf(mx1, __shfl_xor_sync(0xffffffffu, mx1, 1));
        mx1 = fmaxf(mx1, __shfl_xor_sync(0xffffffffu, mx1, 2));
        const float mn0 = fmaxf(mr0, mx0), mn1 = fmaxf(mr1, mx1);
        const float co0 = fast_exp2(mr0 - mn0), co1 = fast_exp2(mr1 - mn1);
        mr0 = mn0; mr1 = mn1;
        float s0 = 0.f, s1 = 0.f;
        #pragma unroll
        for (int nb = 0; nb < 8; nb++) {
            cS[nb][0] = fast_exp2(cS[nb][0] - mn0);
            cS[nb][1] = fast_exp2(cS[nb][1] - mn0);
            cS[nb][2] = fast_exp2(cS[nb][2] - mn1);
            cS[nb][3] = fast_exp2(cS[nb][3] - mn1);
            s0 += cS[nb][0] + cS[nb][1];
            s1 += cS[nb][2] + cS[nb][3];
        }
        s0 += __shfl_xor_sync(0xffffffffu, s0, 1);
        s0 += __shfl_xor_sync(0xffffffffu, s0, 2);
        s1 += __shfl_xor_sync(0xffffffffu, s1, 1);
        s1 += __shfl_xor_sync(0xffffffffu, s1, 2);
        lr0 = lr0 * co0 + s0;
        lr1 = lr1 * co1 + s1;
        #pragma unroll
        for (int nb = 0; nb < 8; nb++) {
            cO[nb][0] *= co0; cO[nb][1] *= co0;
            cO[nb][2] *= co1; cO[nb][3] *= co1;
        }

        // ---- O += P V (P single fp16, V 2-term) ----
        #pragma unroll
        for (int s = 0; s < 4; s++) {
            uint32_t aP[4];
            aP[0] = pack2h(cS[2*s][0],   cS[2*s][1]);
            aP[1] = pack2h(cS[2*s][2],   cS[2*s][3]);
            aP[2] = pack2h(cS[2*s+1][0], cS[2*s+1][1]);
            aP[3] = pack2h(cS[2*s+1][2], cS[2*s+1][3]);
            #pragma unroll
            for (int nbp = 0; nbp < 4; nbp++) {
                const int row = s*16 + (grp & 1)*8 + wi;
                const int cb  = nbp*32 + (grp >> 1)*16;
                const uint32_t off = row*128 + ((uint32_t)cb ^ (uint32_t)((row & 7) << 4));
                uint32_t vh4[4], vl4[4];
                ldsm4t(stb + 16384 + off, vh4);
                ldsm4t(stb + 24576 + off, vl4);
                mma_f16(cO[2*nbp],   aP, vh4[0], vh4[1]);
                mma_f16(cO[2*nbp],   aP, vl4[0], vl4[1]);
                mma_f16(cO[2*nbp+1], aP, vh4[2], vh4[3]);
                mma_f16(cO[2*nbp+1], aP, vl4[2], vl4[3]);
            }
        }
    }

    // ---- normalize + write fp16 ----
    const float i0 = 1.f / lr0, i1 = 1.f / lr1;
    const int t0 = qt*64 + warp*16 + g;
    #pragma unroll
    for (int nb = 0; nb < 8; nb++) {
        const int d = h*HD + nb*8 + t4*2;
        const size_t o0 = (size_t)(b*TT + t0) * DD + d;
        const size_t o1 = o0 + (size_t)8 * DD;
        *(__half2*)(Oh + o0) = __floats2half2_rn(cO[nb][0]*i0, cO[nb][1]*i0);
        *(__half2*)(Oh + o1) = __floats2half2_rn(cO[nb][2]*i1, cO[nb][3]*i1);
    }
}

// ---------------------------------------------------------------------------
extern "C" void kernel_launch(void* const* d_in, const int* in_sizes, int n_in,
                              void* d_out, int out_size)
{
    const float* x  = (const float*)d_in[0];
    const float* Wq = (const float*)d_in[1];
    const float* bq = (const float*)d_in[2];
    const float* Wk = (const float*)d_in[3];
    const float* bk = (const float*)d_in[4];
    const float* Wv = (const float*)d_in[5];
    const float* bv = (const float*)d_in[6];
    const float* Wo = (const float*)d_in[7];
    const float* bo = (const float*)d_in[8];
    float* out = (float*)d_out;

    __half *xh,*qh,*ql,*kh,*kl,*vh,*vl,*ah,*wh,*wl;
    cudaGetSymbolAddress((void**)&xh, g_xh);
    cudaGetSymbolAddress((void**)&qh, g_qh);
    cudaGetSymbolAddress((void**)&ql, g_ql);
    cudaGetSymbolAddress((void**)&kh, g_kh);
    cudaGetSymbolAddress((void**)&kl, g_kl);
    cudaGetSymbolAddress((void**)&vh, g_vh);
    cudaGetSymbolAddress((void**)&vl, g_vl);
    cudaGetSymbolAddress((void**)&ah, g_ah);
    cudaGetSymbolAddress((void**)&wh, g_wh);
    cudaGetSymbolAddress((void**)&wl, g_wl);

    cudaFuncSetAttribute(mma_gemm<0>, cudaFuncAttributeMaxDynamicSharedMemorySize, GEMM_SMEM);
    cudaFuncSetAttribute(mma_gemm<1>, cudaFuncAttributeMaxDynamicSharedMemorySize, GEMM_SMEM);
    cudaFuncSetAttribute(attn_mma,   cudaFuncAttributeMaxDynamicSharedMemorySize, ATT_SMEM);

    const size_t WSZ = (size_t)DD * DD;

    tohalf<<<(MM*DD/4)/256, 256>>>(x, xh);
    transp_split4<<<dim3(32, 32, 4), dim3(32, 8)>>>(Wq, Wk, Wv, Wo, wh, wl);

    mma_gemm<1><<<dim3(DD/128, MM/128, 3), 256, GEMM_SMEM>>>(
        xh, wh, wl, bq, bk, bv, nullptr,
        qh, ql, kh, kl, vh, vl);

    attn_mma<<<dim3(TT/64, BB*HH), 128, ATT_SMEM>>>(qh, kh, kl, vh, vl, ah);

    mma_gemm<0><<<dim3(DD/128, MM/128, 1), 256, GEMM_SMEM>>>(
        ah, wh + 3*WSZ, wl + 3*WSZ, bo, bo, bo, out,
        nullptr, nullptr, nullptr, nullptr, nullptr, nullptr);
}

// round 11
// speedup vs baseline: 1.6664x; 1.2312x over previous
#include <cuda_runtime.h>
#include <cuda_fp16.h>
#include <math.h>
#include <stdint.h>

#define BB 2
#define TT 2048
#define DD 1024
#define HH 16
#define HD 64
#define MM (BB*TT)

// ---------------- scratch ----------------
__device__ __half g_xh[(size_t)MM*DD];
__device__ __half g_qh[(size_t)MM*DD];
__device__ __half g_kh[(size_t)MM*DD];
__device__ __half g_vh[(size_t)MM*DD];
__device__ __half g_ah[(size_t)MM*DD];
__device__ __half g_wh[4*(size_t)DD*DD];
__device__ __half g_wl[4*(size_t)DD*DD];

// ---------------- helpers ----------------
__device__ __forceinline__ uint32_t smem_u32(const void* p) {
    uint32_t a;
    asm("{ .reg .u64 t; cvta.to.shared.u64 t, %1; cvt.u32.u64 %0, t; }" : "=r"(a) : "l"(p));
    return a;
}
__device__ __forceinline__ float fast_exp2(float x) {
    float y; asm("ex2.approx.ftz.f32 %0, %1;" : "=f"(y) : "f"(x)); return y;
}
__device__ __forceinline__ void hsplit(float v, __half& h, __half& l) {
    h = __float2half_rn(v);
    l = __float2half_rn(v - __half2float(h));
}
__device__ __forceinline__ void mma_f16(float* c, const uint32_t* a, uint32_t b0, uint32_t b1) {
    asm("mma.sync.aligned.m16n8k16.row.col.f32.f16.f16.f32 "
        "{%0,%1,%2,%3}, {%4,%5,%6,%7}, {%8,%9}, {%0,%1,%2,%3};"
        : "+f"(c[0]), "+f"(c[1]), "+f"(c[2]), "+f"(c[3])
        : "r"(a[0]), "r"(a[1]), "r"(a[2]), "r"(a[3]), "r"(b0), "r"(b1));
}
__device__ __forceinline__ void ldsm4(uint32_t addr, uint32_t* r) {
    asm volatile("ldmatrix.sync.aligned.m8n8.x4.shared.b16 {%0,%1,%2,%3}, [%4];"
        : "=r"(r[0]), "=r"(r[1]), "=r"(r[2]), "=r"(r[3]) : "r"(addr));
}
__device__ __forceinline__ void ldsm4t(uint32_t addr, uint32_t* r) {
    asm volatile("ldmatrix.sync.aligned.m8n8.x4.trans.shared.b16 {%0,%1,%2,%3}, [%4];"
        : "=r"(r[0]), "=r"(r[1]), "=r"(r[2]), "=r"(r[3]) : "r"(addr));
}
__device__ __forceinline__ void cpa(uint32_t dst, const void* src) {
    asm volatile("cp.async.ca.shared.global [%0], [%1], 16;" :: "r"(dst), "l"(src));
}
__device__ __forceinline__ void commitg() {
    asm volatile("cp.async.commit_group;" ::: "memory");
}
template<int N> __device__ __forceinline__ void waitg() {
    asm volatile("cp.async.wait_group %0;" :: "n"(N) : "memory");
}
__device__ __forceinline__ uint32_t pack2h(float x, float y) {
    uint32_t r; asm("cvt.rn.f16x2.f32 %0, %1, %2;" : "=r"(r) : "f"(y), "f"(x)); return r;
}

// ---------------------------------------------------------------------------
__global__ void tohalf(const float* __restrict__ in, __half* __restrict__ out)
{
    const int i = blockIdx.x * blockDim.x + threadIdx.x;
    float4 v = ((const float4*)in)[i];
    __half2* p = (__half2*)out;
    p[2*i]   = __floats2half2_rn(v.x, v.y);
    p[2*i+1] = __floats2half2_rn(v.z, v.w);
}

// W transposed, scaled by 512, split to fp16 hi/lo
__global__ void transp_split4(const float* __restrict__ W0, const float* __restrict__ W1,
                              const float* __restrict__ W2, const float* __restrict__ W3,
                              __half* __restrict__ Bh, __half* __restrict__ Bl)
{
    __shared__ float t[32][33];
    const int z = blockIdx.z;
    const float* A = (z == 0) ? W0 : (z == 1) ? W1 : (z == 2) ? W2 : W3;
    const size_t zo = (size_t)z * DD * DD;
    const int bx = blockIdx.x * 32, by = blockIdx.y * 32;
    const int x = threadIdx.x, y = threadIdx.y;
    #pragma unroll
    for (int i = 0; i < 32; i += 8)
        t[y + i][x] = A[(size_t)(by + y + i) * DD + bx + x];
    __syncthreads();
    #pragma unroll
    for (int i = 0; i < 32; i += 8) {
        float v = t[x][y + i] * 512.f;
        __half h, l; hsplit(v, h, l);
        const size_t o = zo + (size_t)(bx + y + i) * DD + by + x;
        Bh[o] = h; Bl[o] = l;
    }
}

// ---------------------------------------------------------------------------
// GEMM: fp16 2-term (A single fp16, W split hi/lo pre-scaled by 512).
// MODE 0: fp32 out. MODE 1: merged QKV, single-fp16 scatter to (B,H,T,hd).
// ---------------------------------------------------------------------------
#define G_A  0
#define G_BH 8192
#define G_BL 16384
#define G_STG 24576
#define GEMM_SMEM 49152

#define GEMM_LOAD(IT, STG) { \
    const int k0_ = (IT) * 32; \
    _Pragma("unroll") \
    for (int q_ = 0; q_ < 6; q_++) { \
        int idx_ = q_ * 256 + tid; \
        int buf_ = idx_ >> 9, wi_ = idx_ & 511; \
        int row_ = wi_ >> 2, kc_ = wi_ & 3; \
        uint32_t dst_ = sb + (STG)*G_STG + buf_*8192 + row_*64 + ((kc_ ^ ((row_>>1)&3)) << 4); \
        const __half* src_; \
        if      (buf_ == 0) src_ = Ah  + (size_t)(m0 + row_)*DD + k0_ + kc_*8; \
        else if (buf_ == 1) src_ = Bhi + (size_t)(n0 + row_)*DD + k0_ + kc_*8; \
        else                src_ = Blo + (size_t)(n0 + row_)*DD + k0_ + kc_*8; \
        cpa(dst_, src_); \
    } }

template<int MODE>
__global__ __launch_bounds__(256, 2)
void mma_gemm(const __half* __restrict__ Ah,
              const __half* __restrict__ Whi, const __half* __restrict__ Wlo,
              const float* __restrict__ b0, const float* __restrict__ b1,
              const float* __restrict__ b2,
              float* __restrict__ outf,
              __half* __restrict__ oh0, __half* __restrict__ oh1, __half* __restrict__ oh2)
{
    extern __shared__ __align__(1024) char smem[];
    const uint32_t sb = smem_u32(smem);
    const int tid  = threadIdx.x;
    const int wid  = tid >> 5, lane = tid & 31;
    const int g    = lane >> 2, t4 = lane & 3;
    const int grp  = lane >> 3, wi = lane & 7;
    const int wm   = wid & 3,  wn = wid >> 2;
    const int m0   = blockIdx.y * 128, n0 = blockIdx.x * 128;
    const int z    = blockIdx.z;

    const size_t WSZ = (size_t)DD * DD;
    const __half* Bhi = Whi + (size_t)z * WSZ;
    const __half* Blo = Wlo + (size_t)z * WSZ;
    const float* bias = (z == 0) ? b0 : (z == 1) ? b1 : b2;
    __half* outh = (z == 0) ? oh0 : (z == 1) ? oh1 : oh2;

    float c[2][8][4];
    #pragma unroll
    for (int mb = 0; mb < 2; mb++)
        #pragma unroll
        for (int nb = 0; nb < 8; nb++)
            #pragma unroll
            for (int j = 0; j < 4; j++) c[mb][nb][j] = 0.f;

    GEMM_LOAD(0, 0); commitg();

    for (int it = 0; it < DD/32; it++) {
        waitg<0>();
        __syncthreads();
        if (it + 1 < DD/32) { GEMM_LOAD(it+1, (it+1)&1); commitg(); }
        const uint32_t base = sb + (it & 1) * G_STG;

        #pragma unroll
        for (int ks = 0; ks < 2; ks++) {
            uint32_t ah[2][4];
            #pragma unroll
            for (int mb = 0; mb < 2; mb++) {
                const int row = wm*32 + mb*16 + (grp & 1)*8 + wi;
                const int kb  = ks*32 + (grp >> 1)*16;
                const uint32_t off = row*64 + ((((kb >> 4) ^ ((row >> 1) & 3))) << 4);
                ldsm4(base + G_A + off, ah[mb]);
            }
            #pragma unroll
            for (int nbp = 0; nbp < 4; nbp++) {
                const int rowb = wn*64 + nbp*16 + (grp >> 1)*8 + wi;
                const int kb2  = ks*32 + (grp & 1)*16;
                const uint32_t offb = rowb*64 + ((((kb2 >> 4) ^ ((rowb >> 1) & 3))) << 4);
                uint32_t bh[4], bl[4];
                ldsm4(base + G_BH + offb, bh);
                ldsm4(base + G_BL + offb, bl);
                #pragma unroll
                for (int mb = 0; mb < 2; mb++) {
                    mma_f16(c[mb][2*nbp],   ah[mb], bh[0], bh[1]);
                    mma_f16(c[mb][2*nbp],   ah[mb], bl[0], bl[1]);
                    mma_f16(c[mb][2*nbp+1], ah[mb], bh[2], bh[3]);
                    mma_f16(c[mb][2*nbp+1], ah[mb], bl[2], bl[3]);
                }
            }
        }
    }

    const float INV = 1.f / 512.f;
    #pragma unroll
    for (int mb = 0; mb < 2; mb++) {
        const int row = m0 + wm*32 + mb*16 + g;
        #pragma unroll
        for (int nb = 0; nb < 8; nb++) {
            const int col = n0 + wn*64 + nb*8 + t4*2;
            const float bx = bias[col], by = bias[col+1];
            const float v0x = c[mb][nb][0]*INV + bx, v0y = c[mb][nb][1]*INV + by;
            const float v1x = c[mb][nb][2]*INV + bx, v1y = c[mb][nb][3]*INV + by;
            if (MODE == 0) {
                *(float2*)(outf + (size_t)row * DD + col)       = make_float2(v0x, v0y);
                *(float2*)(outf + (size_t)(row + 8) * DD + col) = make_float2(v1x, v1y);
            } else {
                const int h = col >> 6, d = col & 63;
                const int b0r = row >> 11, t0 = row & (TT-1);
                const int b1r = (row+8) >> 11, t1 = (row+8) & (TT-1);
                const size_t o0 = (((size_t)(b0r*HH + h) * TT + t0) * HD) + d;
                const size_t o1 = (((size_t)(b1r*HH + h) * TT + t1) * HD) + d;
                *(__half2*)(outh + o0) = __floats2half2_rn(v0x, v0y);
                *(__half2*)(outh + o1) = __floats2half2_rn(v1x, v1y);
            }
        }
    }
}

// ---------------------------------------------------------------------------
// Flash attention (single fp16): 64-query tiles, 128 threads, <=3 CTAs/SM.
// S = Qh·Kh; P single fp16; O += P·Vh. 32 S + 32 PV MMAs per warp-tile.
// SMEM 40KB: Q 8K + 2 stages x (K 8K + V 8K).
// ---------------------------------------------------------------------------
#define A_QH 0
#define A_ST(s) (8192 + (s)*16384)
#define ATT_SMEM 40960

#define KV_PREFETCH(KT, STG) { \
    _Pragma("unroll") \
    for (int q_ = 0; q_ < 8; q_++) { \
        int idx_ = q_ * 128 + tid; \
        int arr_ = idx_ >> 9, wi2_ = idx_ & 511; \
        int row_ = wi2_ >> 3, ch_ = wi2_ & 7; \
        uint32_t dst_ = sb + A_ST(STG) + arr_*8192 + row_*128 + ((ch_ ^ (row_ & 7)) << 4); \
        const __half* p_ = arr_ ? Vh : Kh; \
        cpa(dst_, p_ + bo + (size_t)((KT)*64 + row_)*HD + ch_*8); \
    } }

__global__ __launch_bounds__(128, 3)
void attn_mma(const __half* __restrict__ Qh,
              const __half* __restrict__ Kh, const __half* __restrict__ Vh,
              __half* __restrict__ Oh)
{
    extern __shared__ __align__(1024) char smem[];
    const uint32_t sb = smem_u32(smem);
    const int tid  = threadIdx.x, lane = tid & 31, warp = tid >> 5;
    const int g    = lane >> 2, t4 = lane & 3;
    const int grp  = lane >> 3, wi = lane & 7;
    const int qt   = (int)gridDim.x - 1 - (int)blockIdx.x;
    const int bh   = blockIdx.y, b = bh >> 4, h = bh & 15;
    const size_t bo = (size_t)bh * TT * HD;

    // group 0: Q tile + KV stage 0
    #pragma unroll
    for (int q = 0; q < 4; q++) {
        int idx = q * 128 + tid;
        int row = idx >> 3, ch = idx & 7;
        uint32_t dst = sb + A_QH + row*128 + ((ch ^ (row & 7)) << 4);
        cpa(dst, Qh + bo + (size_t)(qt*64 + row)*HD + ch*8);
    }
    KV_PREFETCH(0, 0); commitg();

    const float LOG2E  = 1.4426950408889634f;
    const float scale2 = 0.125f * LOG2E;
    const float slope2 = exp2f(-0.5f * (float)(h + 1)) * LOG2E;

    float cO[8][4];
    #pragma unroll
    for (int nb = 0; nb < 8; nb++)
        #pragma unroll
        for (int j = 0; j < 4; j++) cO[nb][j] = 0.f;
    float mr0 = -1e30f, mr1 = -1e30f, lr0 = 0.f, lr1 = 0.f;
    uint32_t qfh[4][4];

    for (int kt = 0; kt <= qt; kt++) {
        waitg<0>();
        __syncthreads();
        if (kt < qt) { KV_PREFETCH(kt+1, (kt+1)&1); commitg(); }
        const uint32_t stb = sb + A_ST(kt & 1);

        if (kt == 0) {
            #pragma unroll
            for (int s = 0; s < 4; s++) {
                const int row = warp*16 + (grp & 1)*8 + wi;
                const int cb  = s*32 + (grp >> 1)*16;
                const uint32_t off = row*128 + ((uint32_t)cb ^ (uint32_t)((row & 7) << 4));
                ldsm4(sb + A_QH + off, qfh[s]);
            }
        }

        // ---- S = Q K^T (single term) ----
        float cS[8][4];
        #pragma unroll
        for (int nb = 0; nb < 8; nb++)
            #pragma unroll
            for (int j = 0; j < 4; j++) cS[nb][j] = 0.f;

        #pragma unroll
        for (int s = 0; s < 4; s++) {
            #pragma unroll
            for (int nbp = 0; nbp < 4; nbp++) {
                const int row = nbp*16 + (grp >> 1)*8 + wi;
                const int cb  = s*32 + (grp & 1)*16;
                const uint32_t off = row*128 + ((uint32_t)cb ^ (uint32_t)((row & 7) << 4));
                uint32_t kh4[4];
                ldsm4(stb + off, kh4);
                mma_f16(cS[2*nbp],   qfh[s], kh4[0], kh4[1]);
                mma_f16(cS[2*nbp+1], qfh[s], kh4[2], kh4[3]);
            }
        }

        // ---- scale + ALiBi + causal + online softmax ----
        const int r0 = qt*64 + warp*16 + g, r1 = r0 + 8;
        const bool diag = (kt == qt);
        float mx0 = -1e30f, mx1 = -1e30f;
        #pragma unroll
        for (int nb = 0; nb < 8; nb++) {
            const int k0i = kt*64 + nb*8 + t4*2;
            const float b0f = -slope2 * (float)(TT - 1 - k0i);
            const float b1f = -slope2 * (float)(TT - 2 - k0i);
            float v0 = fmaf(cS[nb][0], scale2, b0f);
            float v1 = fmaf(cS[nb][1], scale2, b1f);
            float v2 = fmaf(cS[nb][2], scale2, b0f);
            float v3 = fmaf(cS[nb][3], scale2, b1f);
            if (diag) {
                if (k0i     > r0) v0 = -1e30f;
                if (k0i + 1 > r0) v1 = -1e30f;
                if (k0i     > r1) v2 = -1e30f;
                if (k0i + 1 > r1) v3 = -1e30f;
            }
            cS[nb][0] = v0; cS[nb][1] = v1; cS[nb][2] = v2; cS[nb][3] = v3;
            mx0 = fmaxf(mx0, fmaxf(v0, v1));
            mx1 = fmaxf(mx1, fmaxf(v2, v3));
        }
        mx0 = fmaxf(mx0, __shfl_xor_sync(0xffffffffu, mx0, 1));
        mx0 = fmaxf(mx0, __shfl_xor_sync(0xffffffffu, mx0, 2));
        mx1 = fmaxf(mx1, __shfl_xor_sync(0xffffffffu, mx1, 1));
        mx1 = fmaxf(mx1, __shfl_xor_sync(0xffffffffu, mx1, 2));
        const float mn0 = fmaxf(mr0, mx0), mn1 = fmaxf(mr1, mx1);
        const float co0 = fast_exp2(mr0 - mn0), co1 = fast_exp2(mr1 - mn1);
        mr0 = mn0; mr1 = mn1;
        float s0 = 0.f, s1 = 0.f;
        #pragma unroll
        for (int nb = 0; nb < 8; nb++) {
            cS[nb][0] = fast_exp2(cS[nb][0] - mn0);
            cS[nb][1] = fast_exp2(cS[nb][1] - mn0);
            cS[nb][2] = fast_exp2(cS[nb][2] - mn1);
            cS[nb][3] = fast_exp2(cS[nb][3] - mn1);
            s0 += cS[nb][0] + cS[nb][1];
            s1 += cS[nb][2] + cS[nb][3];
        }
        s0 += __shfl_xor_sync(0xffffffffu, s0, 1);
        s0 += __shfl_xor_sync(0xffffffffu, s0, 2);
        s1 += __shfl_xor_sync(0xffffffffu, s1, 1);
        s1 += __shfl_xor_sync(0xffffffffu, s1, 2);
        lr0 = lr0 * co0 + s0;
        lr1 = lr1 * co1 + s1;
        #pragma unroll
        for (int nb = 0; nb < 8; nb++) {
            cO[nb][0] *= co0; cO[nb][1] *= co0;
            cO[nb][2] *= co1; cO[nb][3] *= co1;
        }

        // ---- O += P V (single term) ----
        #pragma unroll
        for (int s = 0; s < 4; s++) {
            uint32_t aP[4];
            aP[0] = pack2h(cS[2*s][0],   cS[2*s][1]);
            aP[1] = pack2h(cS[2*s][2],   cS[2*s][3]);
            aP[2] = pack2h(cS[2*s+1][0], cS[2*s+1][1]);
            aP[3] = pack2h(cS[2*s+1][2], cS[2*s+1][3]);
            #pragma unroll
            for (int nbp = 0; nbp < 4; nbp++) {
                const int row = s*16 + (grp & 1)*8 + wi;
                const int cb  = nbp*32 + (grp >> 1)*16;
                const uint32_t off = row*128 + ((uint32_t)cb ^ (uint32_t)((row & 7) << 4));
                uint32_t vh4[4];
                ldsm4t(stb + 8192 + off, vh4);
                mma_f16(cO[2*nbp],   aP, vh4[0], vh4[1]);
                mma_f16(cO[2*nbp+1], aP, vh4[2], vh4[3]);
            }
        }
    }

    // ---- normalize + write fp16 ----
    const float i0 = 1.f / lr0, i1 = 1.f / lr1;
    const int t0 = qt*64 + warp*16 + g;
    #pragma unroll
    for (int nb = 0; nb < 8; nb++) {
        const int d = h*HD + nb*8 + t4*2;
        const size_t o0 = (size_t)(b*TT + t0) * DD + d;
        const size_t o1 = o0 + (size_t)8 * DD;
        *(__half2*)(Oh + o0) = __floats2half2_rn(cO[nb][0]*i0, cO[nb][1]*i0);
        *(__half2*)(Oh + o1) = __floats2half2_rn(cO[nb][2]*i1, cO[nb][3]*i1);
    }
}

// ---------------------------------------------------------------------------
extern "C" void kernel_launch(void* const* d_in, const int* in_sizes, int n_in,
                              void* d_out, int out_size)
{
    const float* x  = (const float*)d_in[0];
    const float* Wq = (const float*)d_in[1];
    const float* bq = (const float*)d_in[2];
    const float* Wk = (const float*)d_in[3];
    const float* bk = (const float*)d_in[4];
    const float* Wv = (const float*)d_in[5];
    const float* bv = (const float*)d_in[6];
    const float* Wo = (const float*)d_in[7];
    const float* bo = (const float*)d_in[8];
    float* out = (float*)d_out;

    __half *xh,*qh,*kh,*vh,*ah,*wh,*wl;
    cudaGetSymbolAddress((void**)&xh, g_xh);
    cudaGetSymbolAddress((void**)&qh, g_qh);
    cudaGetSymbolAddress((void**)&kh, g_kh);
    cudaGetSymbolAddress((void**)&vh, g_vh);
    cudaGetSymbolAddress((void**)&ah, g_ah);
    cudaGetSymbolAddress((void**)&wh, g_wh);
    cudaGetSymbolAddress((void**)&wl, g_wl);

    cudaFuncSetAttribute(mma_gemm<0>, cudaFuncAttributeMaxDynamicSharedMemorySize, GEMM_SMEM);
    cudaFuncSetAttribute(mma_gemm<1>, cudaFuncAttributeMaxDynamicSharedMemorySize, GEMM_SMEM);
    cudaFuncSetAttribute(attn_mma,   cudaFuncAttributeMaxDynamicSharedMemorySize, ATT_SMEM);

    const size_t WSZ = (size_t)DD * DD;

    tohalf<<<(MM*DD/4)/256, 256>>>(x, xh);
    transp_split4<<<dim3(32, 32, 4), dim3(32, 8)>>>(Wq, Wk, Wv, Wo, wh, wl);

    mma_gemm<1><<<dim3(DD/128, MM/128, 3), 256, GEMM_SMEM>>>(
        xh, wh, wl, bq, bk, bv, nullptr, qh, kh, vh);

    attn_mma<<<dim3(TT/64, BB*HH), 128, ATT_SMEM>>>(qh, kh, vh, ah);

    mma_gemm<0><<<dim3(DD/128, MM/128, 1), 256, GEMM_SMEM>>>(
        ah, wh + 3*WSZ, wl + 3*WSZ, bo, bo, bo, out,
        nullptr, nullptr, nullptr);
}

// round 12
// speedup vs baseline: 2.2919x; 1.3754x over previous
#include <cuda_runtime.h>
#include <cuda_fp16.h>
#include <math.h>
#include <stdint.h>

#define BB 2
#define TT 2048
#define DD 1024
#define HH 16
#define HD 64
#define MM (BB*TT)

// ---------------- scratch ----------------
__device__ __half g_xh[(size_t)MM*DD];
__device__ __half g_qh[(size_t)MM*DD];
__device__ __half g_kh[(size_t)MM*DD];
__device__ __half g_vh[(size_t)MM*DD];
__device__ __half g_ah[(size_t)MM*DD];
__device__ __half g_wh[4*(size_t)DD*DD];

// ---------------- helpers ----------------
__device__ __forceinline__ uint32_t smem_u32(const void* p) {
    uint32_t a;
    asm("{ .reg .u64 t; cvta.to.shared.u64 t, %1; cvt.u32.u64 %0, t; }" : "=r"(a) : "l"(p));
    return a;
}
__device__ __forceinline__ float fast_exp2(float x) {
    float y; asm("ex2.approx.ftz.f32 %0, %1;" : "=f"(y) : "f"(x)); return y;
}
__device__ __forceinline__ void mma_f16(float* c, const uint32_t* a, uint32_t b0, uint32_t b1) {
    asm("mma.sync.aligned.m16n8k16.row.col.f32.f16.f16.f32 "
        "{%0,%1,%2,%3}, {%4,%5,%6,%7}, {%8,%9}, {%0,%1,%2,%3};"
        : "+f"(c[0]), "+f"(c[1]), "+f"(c[2]), "+f"(c[3])
        : "r"(a[0]), "r"(a[1]), "r"(a[2]), "r"(a[3]), "r"(b0), "r"(b1));
}
__device__ __forceinline__ void ldsm4(uint32_t addr, uint32_t* r) {
    asm volatile("ldmatrix.sync.aligned.m8n8.x4.shared.b16 {%0,%1,%2,%3}, [%4];"
        : "=r"(r[0]), "=r"(r[1]), "=r"(r[2]), "=r"(r[3]) : "r"(addr));
}
__device__ __forceinline__ void ldsm4t(uint32_t addr, uint32_t* r) {
    asm volatile("ldmatrix.sync.aligned.m8n8.x4.trans.shared.b16 {%0,%1,%2,%3}, [%4];"
        : "=r"(r[0]), "=r"(r[1]), "=r"(r[2]), "=r"(r[3]) : "r"(addr));
}
__device__ __forceinline__ void cpa(uint32_t dst, const void* src) {
    asm volatile("cp.async.ca.shared.global [%0], [%1], 16;" :: "r"(dst), "l"(src));
}
__device__ __forceinline__ void commitg() {
    asm volatile("cp.async.commit_group;" ::: "memory");
}
template<int N> __device__ __forceinline__ void waitg() {
    asm volatile("cp.async.wait_group %0;" :: "n"(N) : "memory");
}
__device__ __forceinline__ uint32_t pack2h(float x, float y) {
    uint32_t r; asm("cvt.rn.f16x2.f32 %0, %1, %2;" : "=r"(r) : "f"(y), "f"(x)); return r;
}

// ---------------------------------------------------------------------------
__global__ void tohalf(const float* __restrict__ in, __half* __restrict__ out)
{
    const int i = blockIdx.x * blockDim.x + threadIdx.x;
    float4 v = ((const float4*)in)[i];
    __half2* p = (__half2*)out;
    p[2*i]   = __floats2half2_rn(v.x, v.y);
    p[2*i+1] = __floats2half2_rn(v.z, v.w);
}

// W transposed to plain fp16
__global__ void transp4(const float* __restrict__ W0, const float* __restrict__ W1,
                        const float* __restrict__ W2, const float* __restrict__ W3,
                        __half* __restrict__ Bh)
{
    __shared__ float t[32][33];
    const int z = blockIdx.z;
    const float* A = (z == 0) ? W0 : (z == 1) ? W1 : (z == 2) ? W2 : W3;
    const size_t zo = (size_t)z * DD * DD;
    const int bx = blockIdx.x * 32, by = blockIdx.y * 32;
    const int x = threadIdx.x, y = threadIdx.y;
    #pragma unroll
    for (int i = 0; i < 32; i += 8)
        t[y + i][x] = A[(size_t)(by + y + i) * DD + bx + x];
    __syncthreads();
    #pragma unroll
    for (int i = 0; i < 32; i += 8)
        Bh[zo + (size_t)(bx + y + i) * DD + by + x] = __float2half_rn(t[x][y + i]);
}

// ---------------------------------------------------------------------------
// GEMM: plain fp16 mma.sync + ldmatrix + cp.async double buffer, 1 sync/iter.
// MODE 0: fp32 out. MODE 1: merged QKV, single-fp16 scatter to (B,H,T,hd).
// ---------------------------------------------------------------------------
#define G_A  0
#define G_B  8192
#define G_STG 16384
#define GEMM_SMEM 32768

#define GEMM_LOAD(IT, STG) { \
    const int k0_ = (IT) * 32; \
    _Pragma("unroll") \
    for (int q_ = 0; q_ < 4; q_++) { \
        int idx_ = q_ * 256 + tid; \
        int buf_ = idx_ >> 9, wi_ = idx_ & 511; \
        int row_ = wi_ >> 2, kc_ = wi_ & 3; \
        uint32_t dst_ = sb + (STG)*G_STG + buf_*8192 + row_*64 + ((kc_ ^ ((row_>>1)&3)) << 4); \
        const __half* src_ = buf_ ? (Bh + (size_t)(n0 + row_)*DD + k0_ + kc_*8) \
                                  : (Ah + (size_t)(m0 + row_)*DD + k0_ + kc_*8); \
        cpa(dst_, src_); \
    } }

template<int MODE>
__global__ __launch_bounds__(256, 2)
void mma_gemm(const __half* __restrict__ Ah, const __half* __restrict__ Wh,
              const float* __restrict__ b0, const float* __restrict__ b1,
              const float* __restrict__ b2,
              float* __restrict__ outf,
              __half* __restrict__ oh0, __half* __restrict__ oh1, __half* __restrict__ oh2)
{
    extern __shared__ __align__(1024) char smem[];
    const uint32_t sb = smem_u32(smem);
    const int tid  = threadIdx.x;
    const int wid  = tid >> 5, lane = tid & 31;
    const int g    = lane >> 2, t4 = lane & 3;
    const int grp  = lane >> 3, wi = lane & 7;
    const int wm   = wid & 3,  wn = wid >> 2;
    const int m0   = blockIdx.y * 128, n0 = blockIdx.x * 128;
    const int z    = blockIdx.z;

    const size_t WSZ = (size_t)DD * DD;
    const __half* Bh = Wh + (size_t)z * WSZ;
    const float* bias = (z == 0) ? b0 : (z == 1) ? b1 : b2;
    __half* outh = (z == 0) ? oh0 : (z == 1) ? oh1 : oh2;

    float c[2][8][4];
    #pragma unroll
    for (int mb = 0; mb < 2; mb++)
        #pragma unroll
        for (int nb = 0; nb < 8; nb++)
            #pragma unroll
            for (int j = 0; j < 4; j++) c[mb][nb][j] = 0.f;

    GEMM_LOAD(0, 0); commitg();

    for (int it = 0; it < DD/32; it++) {
        waitg<0>();
        __syncthreads();
        if (it + 1 < DD/32) { GEMM_LOAD(it+1, (it+1)&1); commitg(); }
        const uint32_t base = sb + (it & 1) * G_STG;

        #pragma unroll
        for (int ks = 0; ks < 2; ks++) {
            uint32_t ah[2][4];
            #pragma unroll
            for (int mb = 0; mb < 2; mb++) {
                const int row = wm*32 + mb*16 + (grp & 1)*8 + wi;
                const int kb  = ks*32 + (grp >> 1)*16;
                const uint32_t off = row*64 + ((((kb >> 4) ^ ((row >> 1) & 3))) << 4);
                ldsm4(base + G_A + off, ah[mb]);
            }
            #pragma unroll
            for (int nbp = 0; nbp < 4; nbp++) {
                const int rowb = wn*64 + nbp*16 + (grp >> 1)*8 + wi;
                const int kb2  = ks*32 + (grp & 1)*16;
                const uint32_t offb = rowb*64 + ((((kb2 >> 4) ^ ((rowb >> 1) & 3))) << 4);
                uint32_t bh[4];
                ldsm4(base + G_B + offb, bh);
                #pragma unroll
                for (int mb = 0; mb < 2; mb++) {
                    mma_f16(c[mb][2*nbp],   ah[mb], bh[0], bh[1]);
                    mma_f16(c[mb][2*nbp+1], ah[mb], bh[2], bh[3]);
                }
            }
        }
    }

    #pragma unroll
    for (int mb = 0; mb < 2; mb++) {
        const int row = m0 + wm*32 + mb*16 + g;
        #pragma unroll
        for (int nb = 0; nb < 8; nb++) {
            const int col = n0 + wn*64 + nb*8 + t4*2;
            const float bx = bias[col], by = bias[col+1];
            const float v0x = c[mb][nb][0] + bx, v0y = c[mb][nb][1] + by;
            const float v1x = c[mb][nb][2] + bx, v1y = c[mb][nb][3] + by;
            if (MODE == 0) {
                *(float2*)(outf + (size_t)row * DD + col)       = make_float2(v0x, v0y);
                *(float2*)(outf + (size_t)(row + 8) * DD + col) = make_float2(v1x, v1y);
            } else {
                const int h = col >> 6, d = col & 63;
                const int b0r = row >> 11, t0 = row & (TT-1);
                const int b1r = (row+8) >> 11, t1 = (row+8) & (TT-1);
                const size_t o0 = (((size_t)(b0r*HH + h) * TT + t0) * HD) + d;
                const size_t o1 = (((size_t)(b1r*HH + h) * TT + t1) * HD) + d;
                *(__half2*)(outh + o0) = __floats2half2_rn(v0x, v0y);
                *(__half2*)(outh + o1) = __floats2half2_rn(v1x, v1y);
            }
        }
    }
}

// ---------------------------------------------------------------------------
// Flash attention (single fp16): 64-query tiles, 128 threads, <=3 CTAs/SM.
// S = Qh·Kh; P single fp16; O += P·Vh.
// SMEM 40KB: Q 8K + 2 stages x (K 8K + V 8K).
// ---------------------------------------------------------------------------
#define A_QH 0
#define A_ST(s) (8192 + (s)*16384)
#define ATT_SMEM 40960

#define KV_PREFETCH(KT, STG) { \
    _Pragma("unroll") \
    for (int q_ = 0; q_ < 8; q_++) { \
        int idx_ = q_ * 128 + tid; \
        int arr_ = idx_ >> 9, wi2_ = idx_ & 511; \
        int row_ = wi2_ >> 3, ch_ = wi2_ & 7; \
        uint32_t dst_ = sb + A_ST(STG) + arr_*8192 + row_*128 + ((ch_ ^ (row_ & 7)) << 4); \
        const __half* p_ = arr_ ? Vh : Kh; \
        cpa(dst_, p_ + bo + (size_t)((KT)*64 + row_)*HD + ch_*8); \
    } }

__global__ __launch_bounds__(128, 3)
void attn_mma(const __half* __restrict__ Qh,
              const __half* __restrict__ Kh, const __half* __restrict__ Vh,
              __half* __restrict__ Oh)
{
    extern __shared__ __align__(1024) char smem[];
    const uint32_t sb = smem_u32(smem);
    const int tid  = threadIdx.x, lane = tid & 31, warp = tid >> 5;
    const int g    = lane >> 2, t4 = lane & 3;
    const int grp  = lane >> 3, wi = lane & 7;
    const int qt   = (int)gridDim.x - 1 - (int)blockIdx.x;
    const int bh   = blockIdx.y, b = bh >> 4, h = bh & 15;
    const size_t bo = (size_t)bh * TT * HD;

    #pragma unroll
    for (int q = 0; q < 4; q++) {
        int idx = q * 128 + tid;
        int row = idx >> 3, ch = idx & 7;
        uint32_t dst = sb + A_QH + row*128 + ((ch ^ (row & 7)) << 4);
        cpa(dst, Qh + bo + (size_t)(qt*64 + row)*HD + ch*8);
    }
    KV_PREFETCH(0, 0); commitg();

    const float LOG2E  = 1.4426950408889634f;
    const float scale2 = 0.125f * LOG2E;
    const float slope2 = exp2f(-0.5f * (float)(h + 1)) * LOG2E;

    float cO[8][4];
    #pragma unroll
    for (int nb = 0; nb < 8; nb++)
        #pragma unroll
        for (int j = 0; j < 4; j++) cO[nb][j] = 0.f;
    float mr0 = -1e30f, mr1 = -1e30f, lr0 = 0.f, lr1 = 0.f;
    uint32_t qfh[4][4];

    for (int kt = 0; kt <= qt; kt++) {
        waitg<0>();
        __syncthreads();
        if (kt < qt) { KV_PREFETCH(kt+1, (kt+1)&1); commitg(); }
        const uint32_t stb = sb + A_ST(kt & 1);

        if (kt == 0) {
            #pragma unroll
            for (int s = 0; s < 4; s++) {
                const int row = warp*16 + (grp & 1)*8 + wi;
                const int cb  = s*32 + (grp >> 1)*16;
                const uint32_t off = row*128 + ((uint32_t)cb ^ (uint32_t)((row & 7) << 4));
                ldsm4(sb + A_QH + off, qfh[s]);
            }
        }

        // ---- S = Q K^T ----
        float cS[8][4];
        #pragma unroll
        for (int nb = 0; nb < 8; nb++)
            #pragma unroll
            for (int j = 0; j < 4; j++) cS[nb][j] = 0.f;

        #pragma unroll
        for (int s = 0; s < 4; s++) {
            #pragma unroll
            for (int nbp = 0; nbp < 4; nbp++) {
                const int row = nbp*16 + (grp >> 1)*8 + wi;
                const int cb  = s*32 + (grp & 1)*16;
                const uint32_t off = row*128 + ((uint32_t)cb ^ (uint32_t)((row & 7) << 4));
                uint32_t kh4[4];
                ldsm4(stb + off, kh4);
                mma_f16(cS[2*nbp],   qfh[s], kh4[0], kh4[1]);
                mma_f16(cS[2*nbp+1], qfh[s], kh4[2], kh4[3]);
            }
        }

        // ---- scale + ALiBi + causal + online softmax ----
        const int r0 = qt*64 + warp*16 + g, r1 = r0 + 8;
        const bool diag = (kt == qt);
        float mx0 = -1e30f, mx1 = -1e30f;
        #pragma unroll
        for (int nb = 0; nb < 8; nb++) {
            const int k0i = kt*64 + nb*8 + t4*2;
            const float b0f = -slope2 * (float)(TT - 1 - k0i);
            const float b1f = -slope2 * (float)(TT - 2 - k0i);
            float v0 = fmaf(cS[nb][0], scale2, b0f);
            float v1 = fmaf(cS[nb][1], scale2, b1f);
            float v2 = fmaf(cS[nb][2], scale2, b0f);
            float v3 = fmaf(cS[nb][3], scale2, b1f);
            if (diag) {
                if (k0i     > r0) v0 = -1e30f;
                if (k0i + 1 > r0) v1 = -1e30f;
                if (k0i     > r1) v2 = -1e30f;
                if (k0i + 1 > r1) v3 = -1e30f;
            }
            cS[nb][0] = v0; cS[nb][1] = v1; cS[nb][2] = v2; cS[nb][3] = v3;
            mx0 = fmaxf(mx0, fmaxf(v0, v1));
            mx1 = fmaxf(mx1, fmaxf(v2, v3));
        }
        mx0 = fmaxf(mx0, __shfl_xor_sync(0xffffffffu, mx0, 1));
        mx0 = fmaxf(mx0, __shfl_xor_sync(0xffffffffu, mx0, 2));
        mx1 = fmaxf(mx1, __shfl_xor_sync(0xffffffffu, mx1, 1));
        mx1 = fmaxf(mx1, __shfl_xor_sync(0xffffffffu, mx1, 2));
        const float mn0 = fmaxf(mr0, mx0), mn1 = fmaxf(mr1, mx1);
        const float co0 = fast_exp2(mr0 - mn0), co1 = fast_exp2(mr1 - mn1);
        mr0 = mn0; mr1 = mn1;
        float s0 = 0.f, s1 = 0.f;
        #pragma unroll
        for (int nb = 0; nb < 8; nb++) {
            cS[nb][0] = fast_exp2(cS[nb][0] - mn0);
            cS[nb][1] = fast_exp2(cS[nb][1] - mn0);
            cS[nb][2] = fast_exp2(cS[nb][2] - mn1);
            cS[nb][3] = fast_exp2(cS[nb][3] - mn1);
            s0 += cS[nb][0] + cS[nb][1];
            s1 += cS[nb][2] + cS[nb][3];
        }
        s0 += __shfl_xor_sync(0xffffffffu, s0, 1);
        s0 += __shfl_xor_sync(0xffffffffu, s0, 2);
        s1 += __shfl_xor_sync(0xffffffffu, s1, 1);
        s1 += __shfl_xor_sync(0xffffffffu, s1, 2);
        lr0 = lr0 * co0 + s0;
        lr1 = lr1 * co1 + s1;
        #pragma unroll
        for (int nb = 0; nb < 8; nb++) {
            cO[nb][0] *= co0; cO[nb][1] *= co0;
            cO[nb][2] *= co1; cO[nb][3] *= co1;
        }

        // ---- O += P V ----
        #pragma unroll
        for (int s = 0; s < 4; s++) {
            uint32_t aP[4];
            aP[0] = pack2h(cS[2*s][0],   cS[2*s][1]);
            aP[1] = pack2h(cS[2*s][2],   cS[2*s][3]);
            aP[2] = pack2h(cS[2*s+1][0], cS[2*s+1][1]);
            aP[3] = pack2h(cS[2*s+1][2], cS[2*s+1][3]);
            #pragma unroll
            for (int nbp = 0; nbp < 4; nbp++) {
                const int row = s*16 + (grp & 1)*8 + wi;
                const int cb  = nbp*32 + (grp >> 1)*16;
                const uint32_t off = row*128 + ((uint32_t)cb ^ (uint32_t)((row & 7) << 4));
                uint32_t vh4[4];
                ldsm4t(stb + 8192 + off, vh4);
                mma_f16(cO[2*nbp],   aP, vh4[0], vh4[1]);
                mma_f16(cO[2*nbp+1], aP, vh4[2], vh4[3]);
            }
        }
    }

    // ---- normalize + write fp16 ----
    const float i0 = 1.f / lr0, i1 = 1.f / lr1;
    const int t0 = qt*64 + warp*16 + g;
    #pragma unroll
    for (int nb = 0; nb < 8; nb++) {
        const int d = h*HD + nb*8 + t4*2;
        const size_t o0 = (size_t)(b*TT + t0) * DD + d;
        const size_t o1 = o0 + (size_t)8 * DD;
        *(__half2*)(Oh + o0) = __floats2half2_rn(cO[nb][0]*i0, cO[nb][1]*i0);
        *(__half2*)(Oh + o1) = __floats2half2_rn(cO[nb][2]*i1, cO[nb][3]*i1);
    }
}

// ---------------------------------------------------------------------------
extern "C" void kernel_launch(void* const* d_in, const int* in_sizes, int n_in,
                              void* d_out, int out_size)
{
    const float* x  = (const float*)d_in[0];
    const float* Wq = (const float*)d_in[1];
    const float* bq = (const float*)d_in[2];
    const float* Wk = (const float*)d_in[3];
    const float* bk = (const float*)d_in[4];
    const float* Wv = (const float*)d_in[5];
    const float* bv = (const float*)d_in[6];
    const float* Wo = (const float*)d_in[7];
    const float* bo = (const float*)d_in[8];
    float* out = (float*)d_out;

    __half *xh,*qh,*kh,*vh,*ah,*wh;
    cudaGetSymbolAddress((void**)&xh, g_xh);
    cudaGetSymbolAddress((void**)&qh, g_qh);
    cudaGetSymbolAddress((void**)&kh, g_kh);
    cudaGetSymbolAddress((void**)&vh, g_vh);
    cudaGetSymbolAddress((void**)&ah, g_ah);
    cudaGetSymbolAddress((void**)&wh, g_wh);

    cudaFuncSetAttribute(mma_gemm<0>, cudaFuncAttributeMaxDynamicSharedMemorySize, GEMM_SMEM);
    cudaFuncSetAttribute(mma_gemm<1>, cudaFuncAttributeMaxDynamicSharedMemorySize, GEMM_SMEM);
    cudaFuncSetAttribute(attn_mma,   cudaFuncAttributeMaxDynamicSharedMemorySize, ATT_SMEM);

    const size_t WSZ = (size_t)DD * DD;

    tohalf<<<(MM*DD/4)/256, 256>>>(x, xh);
    transp4<<<dim3(32, 32, 4), dim3(32, 8)>>>(Wq, Wk, Wv, Wo, wh);

    mma_gemm<1><<<dim3(DD/128, MM/128, 3), 256, GEMM_SMEM>>>(
        xh, wh, bq, bk, bv, nullptr, qh, kh, vh);

    attn_mma<<<dim3(TT/64, BB*HH), 128, ATT_SMEM>>>(qh, kh, vh, ah);

    mma_gemm<0><<<dim3(DD/128, MM/128, 1), 256, GEMM_SMEM>>>(
        ah, wh + 3*WSZ, bo, bo, bo, out, nullptr, nullptr, nullptr);
}